// round 11
// baseline (speedup 1.0000x reference)
#include <cuda_runtime.h>
#include <cuda_bf16.h>
#include <cstdint>

#define BB   256
#define TT   512
#define II   300
#define HH   64
#define G3   192
#define KP   320      // K padded: 5 chunks of 64
#define NTOT 384      // 192 fwd gates | 192 bwd gates
#define MTOT (BB * TT)
#define RING_D 8      // gru xp prefetch depth (steps)
#define CPB  4        // gru chains (batches) per block

typedef unsigned long long ull;
typedef uint32_t u32;

__device__ float g_xp[2ull * TT * BB * G3];          // 201 MB scratch
__device__ float g_feat[BB * 256];
__device__ __nv_bfloat16 g_Whi[NTOT * KP];
__device__ __nv_bfloat16 g_Wlo[NTOT * KP];
__device__ __nv_bfloat16 g_xhi[(size_t)MTOT * KP];   // 80 MB
__device__ __nv_bfloat16 g_xlo[(size_t)MTOT * KP];   // 80 MB

// ---------------------------------------------------------------------------
// Helpers (plain sm_80+ features — valid on compute_103)
// ---------------------------------------------------------------------------
__device__ __forceinline__ u32 smem_u32(const void* p) {
    u32 a;
    asm("{ .reg .u64 t; cvta.to.shared.u64 t, %1; cvt.u32.u64 %0, t; }" : "=r"(a) : "l"(p));
    return a;
}
__device__ __forceinline__ void cp16(u32 dst, const void* src) {
    asm volatile("cp.async.cg.shared.global [%0], [%1], 16;" :: "r"(dst), "l"(src));
}
#define CP_COMMIT()  asm volatile("cp.async.commit_group;" ::: "memory")
#define CP_WAIT(n)   asm volatile("cp.async.wait_group %0;" :: "n"(n) : "memory")

__device__ __forceinline__ void ldm4(u32* r, u32 addr) {
    asm volatile("ldmatrix.sync.aligned.m8n8.x4.shared.b16 {%0,%1,%2,%3}, [%4];"
                 : "=r"(r[0]), "=r"(r[1]), "=r"(r[2]), "=r"(r[3]) : "r"(addr));
}
__device__ __forceinline__ void mma_bf16(float* c, const u32* a, u32 b0, u32 b1) {
    asm volatile("mma.sync.aligned.m16n8k16.row.col.f32.bf16.bf16.f32 "
                 "{%0,%1,%2,%3}, {%4,%5,%6,%7}, {%8,%9}, {%0,%1,%2,%3};"
                 : "+f"(c[0]), "+f"(c[1]), "+f"(c[2]), "+f"(c[3])
                 : "r"(a[0]), "r"(a[1]), "r"(a[2]), "r"(a[3]), "r"(b0), "r"(b1));
}
#define SWZ(o) ((o) ^ (((o) >> 3) & 0x70))

// f32x2 (packed fp32 FFMA2) for the GRU
__device__ __forceinline__ ull ffma2(ull a, ull b, ull c) {
    ull d; asm("fma.rn.f32x2 %0, %1, %2, %3;" : "=l"(d) : "l"(a), "l"(b), "l"(c)); return d;
}
union F2U { ull u; float2 f; };
__device__ __forceinline__ float hsum2(ull a) { F2U t; t.u = a; return t.f.x + t.f.y; }

// ---------------------------------------------------------------------------
// Kernel 0a: split W_ih (both dirs) into bf16 hi/lo, K padded to 320.
// ---------------------------------------------------------------------------
__global__ void __launch_bounds__(256)
wsplit_kernel(const float* __restrict__ Wf, const float* __restrict__ Wb)
{
    int i = blockIdx.x * 256 + threadIdx.x;
    if (i >= NTOT * KP) return;
    const int n = i / KP, k = i % KP;
    float v = 0.f;
    if (k < II) v = (n < G3) ? Wf[(size_t)n * II + k] : Wb[(size_t)(n - G3) * II + k];
    __nv_bfloat16 hi = __float2bfloat16(v);
    float lo = v - __bfloat162float(hi);
    g_Whi[i] = hi;
    g_Wlo[i] = __float2bfloat16(lo);
}

// ---------------------------------------------------------------------------
// Kernel 0b: split x into bf16 hi/lo, K padded to 320. One thread = 8 cols.
// ---------------------------------------------------------------------------
__global__ void __launch_bounds__(256)
xsplit_kernel(const float* __restrict__ x)
{
    const int task = blockIdx.x * 256 + threadIdx.x;   // MTOT*40 tasks
    if (task >= MTOT * 40) return;
    const int row = task / 40;
    const int c0  = (task % 40) * 8;

    float a[8];
    const float* src = x + (size_t)row * II + c0;
    float4 v0 = make_float4(0.f, 0.f, 0.f, 0.f), v1 = v0;
    if (c0     <= 296) v0 = *(const float4*)src;
    if (c0 + 4 <= 296) v1 = *(const float4*)(src + 4);
    a[0]=v0.x; a[1]=v0.y; a[2]=v0.z; a[3]=v0.w;
    a[4]=v1.x; a[5]=v1.y; a[6]=v1.z; a[7]=v1.w;

    u32 hi[4], lo[4];
    #pragma unroll
    for (int q = 0; q < 4; q++) {
        __nv_bfloat162 h2 = __floats2bfloat162_rn(a[2*q], a[2*q+1]);
        float l0 = a[2*q]   - __bfloat162float(h2.x);
        float l1 = a[2*q+1] - __bfloat162float(h2.y);
        __nv_bfloat162 l2 = __floats2bfloat162_rn(l0, l1);
        hi[q] = *(u32*)&h2;
        lo[q] = *(u32*)&l2;
    }
    const size_t di = (size_t)row * KP + c0;
    *(uint4*)(g_xhi + di) = make_uint4(hi[0], hi[1], hi[2], hi[3]);
    *(uint4*)(g_xlo + di) = make_uint4(lo[0], lo[1], lo[2], lo[3]);
}

// ---------------------------------------------------------------------------
// Kernel 1: proj GEMM via mma.sync bf16, 3-pass split (hi*hi + hi*lo + lo*hi).
// CTA tile 128(M) x 128(N), 8 warps 2x4 (warp tile 64x32), K-chunk 64,
// 3-stage cp.async pipeline. Grid (3 N fastest, 1024 M) -> L2 A reuse.
// ---------------------------------------------------------------------------
#define STG_BYTES 65536          // 4 tiles x 16 KB
#define OFF_AHI 0
#define OFF_ALO 16384
#define OFF_BHI 32768
#define OFF_BLO 49152
#define PROJ_SMEM (3 * STG_BYTES + 1024)

__global__ void __launch_bounds__(256, 1)
proj_kernel(const float* __restrict__ bf_, const float* __restrict__ bb_)
{
    extern __shared__ char dyn_smem[];
    const u32 base = (smem_u32(dyn_smem) + 1023u) & ~1023u;

    const int tid    = threadIdx.x;
    const int lane   = tid & 31;
    const int wid    = tid >> 5;
    const int warp_m = wid & 1;
    const int warp_n = wid >> 1;
    const int r0     = blockIdx.y * 128; // M tile
    const int n0     = blockIdx.x * 128; // N tile (fastest -> L2 A reuse)

    float acc[4][4][4];
    #pragma unroll
    for (int i = 0; i < 4; i++)
        #pragma unroll
        for (int j = 0; j < 4; j++)
            #pragma unroll
            for (int q = 0; q < 4; q++) acc[i][j][q] = 0.f;

    auto load_stage = [&](int stg, int c) {
        const int k0 = c * 64;
        const u32 sb = base + stg * STG_BYTES;
        #pragma unroll
        for (int it = 0; it < 4; it++) {
            const int t = tid + it * 256;
            const int row = t >> 3, q = t & 7;
            const u32 off = SWZ((u32)(row * 128 + q * 16));
            const size_t asrc = (size_t)(r0 + row) * KP + k0 + q * 8;
            const size_t bsrc = (size_t)(n0 + row) * KP + k0 + q * 8;
            cp16(sb + OFF_AHI + off, g_xhi + asrc);
            cp16(sb + OFF_ALO + off, g_xlo + asrc);
            cp16(sb + OFF_BHI + off, g_Whi + bsrc);
            cp16(sb + OFF_BLO + off, g_Wlo + bsrc);
        }
    };

    load_stage(0, 0); CP_COMMIT();
    load_stage(1, 1); CP_COMMIT();

    const int lr  = lane & 7;
    const int mi4 = lane >> 3;

    int stg = 0;
    for (int c = 0; c < 5; c++) {
        CP_WAIT(1);
        __syncthreads();

        if (c + 2 < 5) {
            load_stage((stg + 2) % 3, c + 2);
            CP_COMMIT();
        } else {
            CP_COMMIT();
        }

        const u32 sb = base + stg * STG_BYTES;

        #pragma unroll
        for (int kk = 0; kk < 4; kk++) {
            const int kb = kk * 32 + (mi4 >> 1) * 16;

            u32 ah[4][4], al[4][4], bh[2][4], bl[2][4];
            #pragma unroll
            for (int mi = 0; mi < 4; mi++) {
                const int row = warp_m * 64 + mi * 16 + (mi4 & 1) * 8 + lr;
                const u32 off = SWZ((u32)(row * 128 + kb));
                ldm4(ah[mi], sb + OFF_AHI + off);
                ldm4(al[mi], sb + OFF_ALO + off);
            }
            #pragma unroll
            for (int g = 0; g < 2; g++) {
                const int row = warp_n * 32 + g * 16 + (mi4 & 1) * 8 + lr;
                const u32 off = SWZ((u32)(row * 128 + kb));
                ldm4(bh[g], sb + OFF_BHI + off);
                ldm4(bl[g], sb + OFF_BLO + off);
            }
            #pragma unroll
            for (int mi = 0; mi < 4; mi++)
                #pragma unroll
                for (int j = 0; j < 4; j++) {
                    const int g = j >> 1, sel = j & 1;
                    mma_bf16(acc[mi][j], ah[mi], bh[g][sel], bh[g][sel + 2]);
                    mma_bf16(acc[mi][j], ah[mi], bl[g][sel], bl[g][sel + 2]);
                    mma_bf16(acc[mi][j], al[mi], bh[g][sel], bh[g][sel + 2]);
                }
        }
        stg = (stg + 1) % 3;
    }

    // ---- epilogue: bias + scatter to g_xp in scan order ----
    #pragma unroll
    for (int j = 0; j < 4; j++) {
        const int col = n0 + warp_n * 32 + j * 8 + (lane & 3) * 2;
        const int dir = (col >= G3) ? 1 : 0;
        const int g   = col - dir * G3;
        const float2 bv = *(const float2*)((dir ? bb_ : bf_) + g);
        #pragma unroll
        for (int mi = 0; mi < 4; mi++) {
            #pragma unroll
            for (int h = 0; h < 2; h++) {
                const int r = r0 + warp_m * 64 + mi * 16 + (lane >> 2) + h * 8;
                const int b = r >> 9, t = r & 511;
                const int s = dir ? (TT - 1 - t) : t;
                float2 o;
                o.x = acc[mi][j][2*h]   + bv.x;
                o.y = acc[mi][j][2*h+1] + bv.y;
                *(float2*)&g_xp[(((size_t)dir * TT + s) * BB + b) * G3 + g] = o;
            }
        }
    }
}

// ---------------------------------------------------------------------------
// Kernel 2: GRU recurrence — 4 chains (same dir => same W_hh) per 128-thread
// block, ONE weight register set, 12 independent accumulator chains per
// thread => deep intra-warp ILP hides dot/activation latency.
// Grid 128 blocks, 1 block/SM (single wave). Thread (2j+half) owns rows
// j, j+64, j+128 half 'half'; shfl_xor(1) combines. Ring depth 8 x 4 chains.
// ---------------------------------------------------------------------------
__device__ __forceinline__ float sigmoid_fast(float a) {
    return 1.f / (1.f + __expf(-a));
}
__device__ __forceinline__ float tanh_fast(float a) {
    float c = fminf(fmaxf(a, -20.f), 20.f);
    float e = __expf(2.f * c);
    return (e - 1.f) / (e + 1.f);
}

__global__ void __launch_bounds__(128, 1)
gru_kernel(const float* __restrict__ Whh_f, const float* __restrict__ bhh_f,
           const float* __restrict__ Whh_b, const float* __restrict__ bhh_b)
{
    __shared__ __align__(16) float sh_h[2][CPB][64];             // 2 KB
    __shared__ __align__(16) float ring[RING_D][CPB][192];       // 24.6 KB

    const int tid  = threadIdx.x;
    const int j    = tid >> 1;          // h unit 0..63
    const int half = tid & 1;           // which 32 h-inputs
    const int blk  = blockIdx.x;        // 0..127
    const int dir  = blk >> 6;
    const int b0   = (blk & 63) * CPB;

    const float* W  = dir ? Whh_b : Whh_f;
    const float* bh = dir ? bhh_b : bhh_f;

    ull wr[16], wz[16], wn[16];
    {
        const ulonglong2* Rr = (const ulonglong2*)(W + (size_t)j * 64         + half * 32);
        const ulonglong2* Rz = (const ulonglong2*)(W + (size_t)(j + 64) * 64  + half * 32);
        const ulonglong2* Rn = (const ulonglong2*)(W + (size_t)(j + 128) * 64 + half * 32);
        #pragma unroll
        for (int q = 0; q < 8; q++) {
            ((ulonglong2*)wr)[q] = Rr[q];
            ((ulonglong2*)wz)[q] = Rz[q];
            ((ulonglong2*)wn)[q] = Rn[q];
        }
    }
    const float br = bh[j], bz = bh[j + 64], bn = bh[j + 128];

    if (half == 0)
        #pragma unroll
        for (int c = 0; c < CPB; c++) sh_h[0][c][j] = 0.f;
    float h_old[CPB];
    #pragma unroll
    for (int c = 0; c < CPB; c++) h_old[c] = 0.f;

    const float* xp_b[CPB];
    #pragma unroll
    for (int c = 0; c < CPB; c++)
        xp_b[c] = g_xp + ((size_t)dir * TT * BB + (b0 + c)) * G3;
    const size_t stride = (size_t)BB * G3;
    const u32 ring_base = smem_u32(ring);

    // Prologue: fill ring slots 0..RING_D-1 (192 16B-tasks per slot).
    #pragma unroll
    for (int d = 0; d < RING_D; d++) {
        for (int tt = tid; tt < 48 * CPB; tt += 128) {
            const int c = tt / 48, q = tt % 48;
            cp16(ring_base + (u32)(d * (CPB*768) + c * 768 + q * 16),
                 xp_b[c] + (size_t)d * stride + q * 4);
        }
        CP_COMMIT();
    }
    CP_WAIT(RING_D - 1);
    __syncthreads();

    #pragma unroll 1
    for (int s = 0; s < TT; s++) {
        const int slot = s & (RING_D - 1);
        float xr[CPB], xz[CPB], xn[CPB];
        #pragma unroll
        for (int c = 0; c < CPB; c++) {
            const float* xp = ring[slot][c];
            xr[c] = xp[j];
            xz[c] = xp[j + 64];
            xn[c] = xp[j + 128];
        }

        const int pp = s & 1;
        ull ar[CPB], az[CPB], an[CPB];
        #pragma unroll
        for (int c = 0; c < CPB; c++) { ar[c] = 0ull; az[c] = 0ull; an[c] = 0ull; }

        #pragma unroll
        for (int q = 0; q < 8; q++) {
            #pragma unroll
            for (int c = 0; c < CPB; c++) {
                ulonglong2 h2 = ((const ulonglong2*)&sh_h[pp][c][half * 32])[q];
                ar[c] = ffma2(wr[2*q],   h2.x, ar[c]);
                az[c] = ffma2(wz[2*q],   h2.x, az[c]);
                an[c] = ffma2(wn[2*q],   h2.x, an[c]);
                ar[c] = ffma2(wr[2*q+1], h2.y, ar[c]);
                az[c] = ffma2(wz[2*q+1], h2.y, az[c]);
                an[c] = ffma2(wn[2*q+1], h2.y, an[c]);
            }
        }

        float hnew[CPB];
        #pragma unroll
        for (int c = 0; c < CPB; c++) {
            float gr = hsum2(ar[c]), gz = hsum2(az[c]), gn = hsum2(an[c]);
            gr += __shfl_xor_sync(0xffffffffu, gr, 1);
            gz += __shfl_xor_sync(0xffffffffu, gz, 1);
            gn += __shfl_xor_sync(0xffffffffu, gn, 1);
            gr += br; gz += bz; gn += bn;

            const float r = sigmoid_fast(xr[c] + gr);
            const float z = sigmoid_fast(xz[c] + gz);
            const float n = tanh_fast(xn[c] + r * gn);
            hnew[c] = (1.f - z) * n + z * h_old[c];
            h_old[c] = hnew[c];
        }

        if (half == 0) {
            #pragma unroll
            for (int c = 0; c < CPB; c++) sh_h[1 - pp][c][j] = hnew[c];
            if (s == 0)
                #pragma unroll
                for (int c = 0; c < CPB; c++)
                    g_feat[(b0 + c) * 256 + (dir ? 192 : 0) + j] = hnew[c];
        }

        CP_WAIT(RING_D - 2);
        __syncthreads();

        // refill slot s%D with step (s+RING_D)%TT (wrap -> unused, keeps groups uniform)
        const int sn = (s + RING_D) & (TT - 1);
        for (int tt = tid; tt < 48 * CPB; tt += 128) {
            const int c = tt / 48, q = tt % 48;
            cp16(ring_base + (u32)(slot * (CPB*768) + c * 768 + q * 16),
                 xp_b[c] + (size_t)sn * stride + q * 4);
        }
        CP_COMMIT();
    }

    if (half == 0)
        #pragma unroll
        for (int c = 0; c < CPB; c++)
            g_feat[(b0 + c) * 256 + (dir ? 64 : 128) + j] = h_old[c];
}

// ---------------------------------------------------------------------------
// Kernel 3: head. 8 warps per block, one warp per batch row; 32 blocks.
// ---------------------------------------------------------------------------
__global__ void __launch_bounds__(256)
head_kernel(const float* __restrict__ W1, const float* __restrict__ b1,
            const float* __restrict__ W2, const float* __restrict__ b2,
            float* __restrict__ out)
{
    const int wid = threadIdx.x >> 5;
    const int j   = threadIdx.x & 31;
    const int b   = blockIdx.x * 8 + wid;
    const float* f = g_feat + b * 256;
    const float* w = W1 + (size_t)j * 256;

    float acc = b1[j];
    #pragma unroll 8
    for (int k = 0; k < 256; k += 4) {
        float4 fv = *(const float4*)(f + k);
        float4 wv = *(const float4*)(w + k);
        acc += fv.x * wv.x + fv.y * wv.y + fv.z * wv.z + fv.w * wv.w;
    }
    acc = (acc >= 0.f) ? acc : 0.01f * acc;
    float v = acc * W2[j];
    #pragma unroll
    for (int off = 16; off; off >>= 1)
        v += __shfl_down_sync(0xffffffffu, v, off);
    if (j == 0) out[b] = v + b2[0];
}

// ---------------------------------------------------------------------------
extern "C" void kernel_launch(void* const* d_in, const int* in_sizes, int n_in,
                              void* d_out, int out_size)
{
    const float* x      = (const float*)d_in[0];
    const float* W_ih_f = (const float*)d_in[1];
    const float* W_hh_f = (const float*)d_in[2];
    const float* b_ih_f = (const float*)d_in[3];
    const float* b_hh_f = (const float*)d_in[4];
    const float* W_ih_b = (const float*)d_in[5];
    const float* W_hh_b = (const float*)d_in[6];
    const float* b_ih_b = (const float*)d_in[7];
    const float* b_hh_b = (const float*)d_in[8];
    const float* W1     = (const float*)d_in[9];
    const float* b1     = (const float*)d_in[10];
    const float* W2     = (const float*)d_in[11];
    const float* b2     = (const float*)d_in[12];
    float* out = (float*)d_out;

    cudaFuncSetAttribute(proj_kernel, cudaFuncAttributeMaxDynamicSharedMemorySize, PROJ_SMEM);

    wsplit_kernel<<<(NTOT * KP + 255) / 256, 256>>>(W_ih_f, W_ih_b);
    xsplit_kernel<<<(MTOT * 40 + 255) / 256, 256>>>(x);
    proj_kernel<<<dim3(3, 1024), 256, PROJ_SMEM>>>(b_ih_f, b_ih_b);
    gru_kernel<<<128, 128>>>(W_hh_f, b_hh_f, W_hh_b, b_hh_b);
    head_kernel<<<32, 256>>>(W1, b1, W2, b2, out);
}

// round 12
// speedup vs baseline: 1.2717x; 1.2717x over previous
#include <cuda_runtime.h>
#include <cuda_bf16.h>
#include <cstdint>

#define BB   256
#define TT   512
#define II   300
#define HH   64
#define G3   192
#define KP   320      // K padded: 5 chunks of 64
#define NTOT 384      // 192 fwd gates | 192 bwd gates
#define MTOT (BB * TT)
#define RING_D 8      // gru xp prefetch depth (steps)

typedef unsigned long long ull;
typedef uint32_t u32;

__device__ float g_xp[2ull * TT * BB * G3];          // 201 MB scratch
__device__ float g_feat[BB * 256];
__device__ __nv_bfloat16 g_Whi[NTOT * KP];
__device__ __nv_bfloat16 g_Wlo[NTOT * KP];
__device__ __nv_bfloat16 g_xhi[(size_t)MTOT * KP];   // 80 MB
__device__ __nv_bfloat16 g_xlo[(size_t)MTOT * KP];   // 80 MB

// ---------------------------------------------------------------------------
// Helpers (plain sm_80+ features — valid on compute_103)
// ---------------------------------------------------------------------------
__device__ __forceinline__ u32 smem_u32(const void* p) {
    u32 a;
    asm("{ .reg .u64 t; cvta.to.shared.u64 t, %1; cvt.u32.u64 %0, t; }" : "=r"(a) : "l"(p));
    return a;
}
__device__ __forceinline__ void cp16(u32 dst, const void* src) {
    asm volatile("cp.async.cg.shared.global [%0], [%1], 16;" :: "r"(dst), "l"(src));
}
#define CP_COMMIT()  asm volatile("cp.async.commit_group;" ::: "memory")
#define CP_WAIT(n)   asm volatile("cp.async.wait_group %0;" :: "n"(n) : "memory")

__device__ __forceinline__ void ldm4(u32* r, u32 addr) {
    asm volatile("ldmatrix.sync.aligned.m8n8.x4.shared.b16 {%0,%1,%2,%3}, [%4];"
                 : "=r"(r[0]), "=r"(r[1]), "=r"(r[2]), "=r"(r[3]) : "r"(addr));
}
__device__ __forceinline__ void mma_bf16(float* c, const u32* a, u32 b0, u32 b1) {
    asm volatile("mma.sync.aligned.m16n8k16.row.col.f32.bf16.bf16.f32 "
                 "{%0,%1,%2,%3}, {%4,%5,%6,%7}, {%8,%9}, {%0,%1,%2,%3};"
                 : "+f"(c[0]), "+f"(c[1]), "+f"(c[2]), "+f"(c[3])
                 : "r"(a[0]), "r"(a[1]), "r"(a[2]), "r"(a[3]), "r"(b0), "r"(b1));
}
#define SWZ(o) ((o) ^ (((o) >> 3) & 0x70))

// f32x2 (packed fp32 FFMA2) for the GRU
__device__ __forceinline__ ull ffma2(ull a, ull b, ull c) {
    ull d; asm("fma.rn.f32x2 %0, %1, %2, %3;" : "=l"(d) : "l"(a), "l"(b), "l"(c)); return d;
}
union F2U { ull u; float2 f; };
__device__ __forceinline__ float hsum2(ull a) { F2U t; t.u = a; return t.f.x + t.f.y; }

// ---------------------------------------------------------------------------
// Kernel 0a: split W_ih (both dirs) into bf16 hi/lo, K padded to 320.
// ---------------------------------------------------------------------------
__global__ void __launch_bounds__(256)
wsplit_kernel(const float* __restrict__ Wf, const float* __restrict__ Wb)
{
    int i = blockIdx.x * 256 + threadIdx.x;
    if (i >= NTOT * KP) return;
    const int n = i / KP, k = i % KP;
    float v = 0.f;
    if (k < II) v = (n < G3) ? Wf[(size_t)n * II + k] : Wb[(size_t)(n - G3) * II + k];
    __nv_bfloat16 hi = __float2bfloat16(v);
    float lo = v - __bfloat162float(hi);
    g_Whi[i] = hi;
    g_Wlo[i] = __float2bfloat16(lo);
}

// ---------------------------------------------------------------------------
// Kernel 0b: split x into bf16 hi/lo, K padded to 320. One thread = 8 cols.
// ---------------------------------------------------------------------------
__global__ void __launch_bounds__(256)
xsplit_kernel(const float* __restrict__ x)
{
    const int task = blockIdx.x * 256 + threadIdx.x;   // MTOT*40 tasks
    if (task >= MTOT * 40) return;
    const int row = task / 40;
    const int c0  = (task % 40) * 8;

    float a[8];
    const float* src = x + (size_t)row * II + c0;
    float4 v0 = make_float4(0.f, 0.f, 0.f, 0.f), v1 = v0;
    if (c0     <= 296) v0 = *(const float4*)src;
    if (c0 + 4 <= 296) v1 = *(const float4*)(src + 4);
    a[0]=v0.x; a[1]=v0.y; a[2]=v0.z; a[3]=v0.w;
    a[4]=v1.x; a[5]=v1.y; a[6]=v1.z; a[7]=v1.w;

    u32 hi[4], lo[4];
    #pragma unroll
    for (int q = 0; q < 4; q++) {
        __nv_bfloat162 h2 = __floats2bfloat162_rn(a[2*q], a[2*q+1]);
        float l0 = a[2*q]   - __bfloat162float(h2.x);
        float l1 = a[2*q+1] - __bfloat162float(h2.y);
        __nv_bfloat162 l2 = __floats2bfloat162_rn(l0, l1);
        hi[q] = *(u32*)&h2;
        lo[q] = *(u32*)&l2;
    }
    const size_t di = (size_t)row * KP + c0;
    *(uint4*)(g_xhi + di) = make_uint4(hi[0], hi[1], hi[2], hi[3]);
    *(uint4*)(g_xlo + di) = make_uint4(lo[0], lo[1], lo[2], lo[3]);
}

// ---------------------------------------------------------------------------
// Kernel 1: proj GEMM via mma.sync bf16, 3-pass split (hi*hi + hi*lo + lo*hi).
// CTA tile 256(M) x 128(N), 512 threads = 16 warps as 4m x 4n (warp tile
// 64x32 — unchanged fragment math). K-chunk 64, 2-stage cp.async pipeline.
// 16 warps/SM (occ 50%) hides pipeline bubbles that bound the 8-warp version.
// Grid (3 N fastest, 512 M) -> A served from L2 for 2 of 3 N-tiles.
// ---------------------------------------------------------------------------
#define STG_BYTES 98304          // A hi 32K | A lo 32K | B hi 16K | B lo 16K
#define OFF_AHI 0
#define OFF_ALO 32768
#define OFF_BHI 65536
#define OFF_BLO 81920
#define PROJ_SMEM (2 * STG_BYTES + 1024)

__global__ void __launch_bounds__(512, 1)
proj_kernel(const float* __restrict__ bf_, const float* __restrict__ bb_)
{
    extern __shared__ char dyn_smem[];
    const u32 base = (smem_u32(dyn_smem) + 1023u) & ~1023u;

    const int tid    = threadIdx.x;
    const int lane   = tid & 31;
    const int wid    = tid >> 5;         // 0..15
    const int warp_m = wid & 3;          // 0..3
    const int warp_n = wid >> 2;         // 0..3
    const int r0     = blockIdx.y * 256; // M tile
    const int n0     = blockIdx.x * 128; // N tile (fastest -> L2 A reuse)

    float acc[4][4][4];
    #pragma unroll
    for (int i = 0; i < 4; i++)
        #pragma unroll
        for (int j = 0; j < 4; j++)
            #pragma unroll
            for (int q = 0; q < 4; q++) acc[i][j][q] = 0.f;

    auto load_stage = [&](int stg, int c) {
        const int k0 = c * 64;
        const u32 sb = base + stg * STG_BYTES;
        // A: 256 rows x 8 kgroups = 2048 tasks (hi+lo per task)
        #pragma unroll
        for (int it = 0; it < 4; it++) {
            const int t = tid + it * 512;
            const int row = t >> 3, q = t & 7;
            const u32 off = SWZ((u32)(row * 128 + q * 16));
            const size_t asrc = (size_t)(r0 + row) * KP + k0 + q * 8;
            cp16(sb + OFF_AHI + off, g_xhi + asrc);
            cp16(sb + OFF_ALO + off, g_xlo + asrc);
        }
        // B: 128 rows x 8 kgroups = 1024 tasks (hi+lo per task)
        #pragma unroll
        for (int it = 0; it < 2; it++) {
            const int t = tid + it * 512;
            const int row = t >> 3, q = t & 7;
            const u32 off = SWZ((u32)(row * 128 + q * 16));
            const size_t bsrc = (size_t)(n0 + row) * KP + k0 + q * 8;
            cp16(sb + OFF_BHI + off, g_Whi + bsrc);
            cp16(sb + OFF_BLO + off, g_Wlo + bsrc);
        }
    };

    load_stage(0, 0); CP_COMMIT();

    const int lr  = lane & 7;
    const int mi4 = lane >> 3;

    for (int c = 0; c < 5; c++) {
        if (c + 1 < 5) { load_stage((c + 1) & 1, c + 1); CP_COMMIT(); CP_WAIT(1); }
        else           { CP_WAIT(0); }
        __syncthreads();

        const u32 sb = base + (c & 1) * STG_BYTES;

        #pragma unroll
        for (int kk = 0; kk < 4; kk++) {
            const int kb = kk * 32 + (mi4 >> 1) * 16;

            u32 ah[4][4], al[4][4], bh[2][4], bl[2][4];
            #pragma unroll
            for (int mi = 0; mi < 4; mi++) {
                const int row = warp_m * 64 + mi * 16 + (mi4 & 1) * 8 + lr;
                const u32 off = SWZ((u32)(row * 128 + kb));
                ldm4(ah[mi], sb + OFF_AHI + off);
                ldm4(al[mi], sb + OFF_ALO + off);
            }
            #pragma unroll
            for (int g = 0; g < 2; g++) {
                const int row = warp_n * 32 + g * 16 + (mi4 & 1) * 8 + lr;
                const u32 off = SWZ((u32)(row * 128 + kb));
                ldm4(bh[g], sb + OFF_BHI + off);
                ldm4(bl[g], sb + OFF_BLO + off);
            }
            #pragma unroll
            for (int mi = 0; mi < 4; mi++)
                #pragma unroll
                for (int j = 0; j < 4; j++) {
                    const int g = j >> 1, sel = j & 1;
                    mma_bf16(acc[mi][j], ah[mi], bh[g][sel], bh[g][sel + 2]);
                    mma_bf16(acc[mi][j], ah[mi], bl[g][sel], bl[g][sel + 2]);
                    mma_bf16(acc[mi][j], al[mi], bh[g][sel], bh[g][sel + 2]);
                }
        }
        __syncthreads();   // all warps done with this stage before its reload
    }

    // ---- epilogue: bias + scatter to g_xp in scan order ----
    #pragma unroll
    for (int j = 0; j < 4; j++) {
        const int col = n0 + warp_n * 32 + j * 8 + (lane & 3) * 2;
        const int dir = (col >= G3) ? 1 : 0;
        const int g   = col - dir * G3;
        const float2 bv = *(const float2*)((dir ? bb_ : bf_) + g);
        #pragma unroll
        for (int mi = 0; mi < 4; mi++) {
            #pragma unroll
            for (int h = 0; h < 2; h++) {
                const int r = r0 + warp_m * 64 + mi * 16 + (lane >> 2) + h * 8;
                const int b = r >> 9, t = r & 511;
                const int s = dir ? (TT - 1 - t) : t;
                float2 o;
                o.x = acc[mi][j][2*h]   + bv.x;
                o.y = acc[mi][j][2*h+1] + bv.y;
                *(float2*)&g_xp[(((size_t)dir * TT + s) * BB + b) * G3 + g] = o;
            }
        }
    }
}

// ---------------------------------------------------------------------------
// Kernel 2: GRU recurrence — R7 config verbatim (proven 323us; both
// restructure attempts regressed). 1 chain per 128-thread block, 4 blocks/SM.
// ---------------------------------------------------------------------------
__device__ __forceinline__ float sigmoid_fast(float a) {
    return 1.f / (1.f + __expf(-a));
}
__device__ __forceinline__ float tanh_fast(float a) {
    float c = fminf(fmaxf(a, -20.f), 20.f);
    float e = __expf(2.f * c);
    return (e - 1.f) / (e + 1.f);
}

__global__ void __launch_bounds__(128, 4)
gru_kernel(const float* __restrict__ Whh_f, const float* __restrict__ bhh_f,
           const float* __restrict__ Whh_b, const float* __restrict__ bhh_b)
{
    __shared__ __align__(16) float sh_h[2][64];
    __shared__ __align__(16) float ring[RING_D][192];

    const int tid  = threadIdx.x;
    const int j    = tid >> 1;
    const int half = tid & 1;
    const int dir  = blockIdx.x >> 8;
    const int b    = blockIdx.x & 255;

    const float* W  = dir ? Whh_b : Whh_f;
    const float* bh = dir ? bhh_b : bhh_f;

    ull wr[16], wz[16], wn[16];
    {
        const ulonglong2* Rr = (const ulonglong2*)(W + (size_t)j * 64         + half * 32);
        const ulonglong2* Rz = (const ulonglong2*)(W + (size_t)(j + 64) * 64  + half * 32);
        const ulonglong2* Rn = (const ulonglong2*)(W + (size_t)(j + 128) * 64 + half * 32);
        #pragma unroll
        for (int q = 0; q < 8; q++) {
            ((ulonglong2*)wr)[q] = Rr[q];
            ((ulonglong2*)wz)[q] = Rz[q];
            ((ulonglong2*)wn)[q] = Rn[q];
        }
    }
    const float br = bh[j], bz = bh[j + 64], bn = bh[j + 128];

    if (tid < 64) sh_h[0][tid] = 0.f;
    float h_old = 0.f;

    const float* xp_b = g_xp + ((size_t)dir * TT * BB + b) * G3;
    const size_t stride = (size_t)BB * G3;
    const u32 ring_base = smem_u32(ring);

    #pragma unroll
    for (int d = 0; d < RING_D; d++) {
        if (tid < 48)
            cp16(ring_base + (u32)(d * 768 + tid * 16),
                 xp_b + (size_t)d * stride + tid * 4);
        CP_COMMIT();
    }
    CP_WAIT(RING_D - 1);
    __syncthreads();

    #pragma unroll 1
    for (int s = 0; s < TT; s++) {
        const int slot = s & (RING_D - 1);
        const float* xp = ring[slot];
        const float xr = xp[j];
        const float xz = xp[j + 64];
        const float xn = xp[j + 128];

        const int pp = s & 1;
        const ulonglong2* hp = (const ulonglong2*)&sh_h[pp][half * 32];
        ull ar = 0ull, az = 0ull, an = 0ull;
        #pragma unroll
        for (int q = 0; q < 8; q++) {
            ulonglong2 h2 = hp[q];
            ar = ffma2(wr[2*q],   h2.x, ar);
            az = ffma2(wz[2*q],   h2.x, az);
            an = ffma2(wn[2*q],   h2.x, an);
            ar = ffma2(wr[2*q+1], h2.y, ar);
            az = ffma2(wz[2*q+1], h2.y, az);
            an = ffma2(wn[2*q+1], h2.y, an);
        }
        float gr = hsum2(ar), gz = hsum2(az), gn = hsum2(an);
        gr += __shfl_xor_sync(0xffffffffu, gr, 1);
        gz += __shfl_xor_sync(0xffffffffu, gz, 1);
        gn += __shfl_xor_sync(0xffffffffu, gn, 1);
        gr += br; gz += bz; gn += bn;

        const float r = sigmoid_fast(xr + gr);
        const float z = sigmoid_fast(xz + gz);
        const float n = tanh_fast(xn + r * gn);
        const float hnew = (1.f - z) * n + z * h_old;
        h_old = hnew;

        if (half == 0) {
            sh_h[1 - pp][j] = hnew;
            if (s == 0)
                g_feat[b * 256 + (dir ? 192 : 0) + j] = hnew;
        }

        CP_WAIT(RING_D - 2);
        __syncthreads();

        if (tid < 48)
            cp16(ring_base + (u32)(slot * 768 + tid * 16),
                 xp_b + (size_t)((s + RING_D) & (TT - 1)) * stride + tid * 4);
        CP_COMMIT();
    }

    if (half == 0)
        g_feat[b * 256 + (dir ? 64 : 128) + j] = h_old;
}

// ---------------------------------------------------------------------------
// Kernel 3: head. 8 warps per block, one warp per batch row; 32 blocks.
// ---------------------------------------------------------------------------
__global__ void __launch_bounds__(256)
head_kernel(const float* __restrict__ W1, const float* __restrict__ b1,
            const float* __restrict__ W2, const float* __restrict__ b2,
            float* __restrict__ out)
{
    const int wid = threadIdx.x >> 5;
    const int j   = threadIdx.x & 31;
    const int b   = blockIdx.x * 8 + wid;
    const float* f = g_feat + b * 256;
    const float* w = W1 + (size_t)j * 256;

    float acc = b1[j];
    #pragma unroll 8
    for (int k = 0; k < 256; k += 4) {
        float4 fv = *(const float4*)(f + k);
        float4 wv = *(const float4*)(w + k);
        acc += fv.x * wv.x + fv.y * wv.y + fv.z * wv.z + fv.w * wv.w;
    }
    acc = (acc >= 0.f) ? acc : 0.01f * acc;
    float v = acc * W2[j];
    #pragma unroll
    for (int off = 16; off; off >>= 1)
        v += __shfl_down_sync(0xffffffffu, v, off);
    if (j == 0) out[b] = v + b2[0];
}

// ---------------------------------------------------------------------------
extern "C" void kernel_launch(void* const* d_in, const int* in_sizes, int n_in,
                              void* d_out, int out_size)
{
    const float* x      = (const float*)d_in[0];
    const float* W_ih_f = (const float*)d_in[1];
    const float* W_hh_f = (const float*)d_in[2];
    const float* b_ih_f = (const float*)d_in[3];
    const float* b_hh_f = (const float*)d_in[4];
    const float* W_ih_b = (const float*)d_in[5];
    const float* W_hh_b = (const float*)d_in[6];
    const float* b_ih_b = (const float*)d_in[7];
    const float* b_hh_b = (const float*)d_in[8];
    const float* W1     = (const float*)d_in[9];
    const float* b1     = (const float*)d_in[10];
    const float* W2     = (const float*)d_in[11];
    const float* b2     = (const float*)d_in[12];
    float* out = (float*)d_out;

    cudaFuncSetAttribute(proj_kernel, cudaFuncAttributeMaxDynamicSharedMemorySize, PROJ_SMEM);

    wsplit_kernel<<<(NTOT * KP + 255) / 256, 256>>>(W_ih_f, W_ih_b);
    xsplit_kernel<<<(MTOT * 40 + 255) / 256, 256>>>(x);
    proj_kernel<<<dim3(3, 512), 512, PROJ_SMEM>>>(b_ih_f, b_ih_b);
    gru_kernel<<<512, 128>>>(W_hh_f, b_hh_f, W_hh_b, b_hh_b);
    head_kernel<<<32, 256>>>(W1, b1, W2, b2, out);
}

// round 13
// speedup vs baseline: 1.5317x; 1.2045x over previous
#include <cuda_runtime.h>
#include <cuda_bf16.h>
#include <cstdint>

#define BB   256
#define TT   512
#define II   300
#define HH   64
#define G3   192
#define KP   320      // K padded: 5 chunks of 64
#define NTOT 384      // 192 fwd gates | 192 bwd gates
#define MTOT (BB * TT)
#define RING_D 8      // gru xp prefetch depth (steps)
#define ROWF 68       // smem floats per row (68 mod 32 = 4 -> conflict-free frags)

typedef unsigned long long ull;
typedef uint32_t u32;

__device__ float g_xp[2ull * TT * BB * G3];          // 201 MB scratch
__device__ float g_feat[BB * 256];
__device__ float g_xt[(size_t)MTOT * KP];            // 167 MB x in tf32 (padded)
__device__ float g_wt[NTOT * KP];                    // W in tf32 (padded, both dirs)

// ---------------------------------------------------------------------------
// Helpers (plain sm_80+ features — valid on compute_103)
// ---------------------------------------------------------------------------
__device__ __forceinline__ u32 smem_u32(const void* p) {
    u32 a;
    asm("{ .reg .u64 t; cvta.to.shared.u64 t, %1; cvt.u32.u64 %0, t; }" : "=r"(a) : "l"(p));
    return a;
}
__device__ __forceinline__ void cp16(u32 dst, const void* src) {
    asm volatile("cp.async.cg.shared.global [%0], [%1], 16;" :: "r"(dst), "l"(src));
}
#define CP_COMMIT()  asm volatile("cp.async.commit_group;" ::: "memory")
#define CP_WAIT(n)   asm volatile("cp.async.wait_group %0;" :: "n"(n) : "memory")

__device__ __forceinline__ void mma_tf32(float* c, const u32* a, u32 b0, u32 b1) {
    asm volatile("mma.sync.aligned.m16n8k8.row.col.f32.tf32.tf32.f32 "
                 "{%0,%1,%2,%3}, {%4,%5,%6,%7}, {%8,%9}, {%0,%1,%2,%3};"
                 : "+f"(c[0]), "+f"(c[1]), "+f"(c[2]), "+f"(c[3])
                 : "r"(a[0]), "r"(a[1]), "r"(a[2]), "r"(a[3]), "r"(b0), "r"(b1));
}
// round fp32 -> tf32 (RNA, unbiased) stored back as fp32 bits
__device__ __forceinline__ float tf32r(float v) {
    u32 o; asm("cvt.rna.tf32.f32 %0, %1;" : "=r"(o) : "f"(v));
    return __uint_as_float(o);
}

// f32x2 (packed fp32 FFMA2) for the GRU
__device__ __forceinline__ ull ffma2(ull a, ull b, ull c) {
    ull d; asm("fma.rn.f32x2 %0, %1, %2, %3;" : "=l"(d) : "l"(a), "l"(b), "l"(c)); return d;
}
union F2U { ull u; float2 f; };
__device__ __forceinline__ float hsum2(ull a) { F2U t; t.u = a; return t.f.x + t.f.y; }

// ---------------------------------------------------------------------------
// Kernel 0a: W_ih (both dirs) -> tf32-rounded fp32, K padded to 320.
// ---------------------------------------------------------------------------
__global__ void __launch_bounds__(256)
wprep_kernel(const float* __restrict__ Wf, const float* __restrict__ Wb)
{
    int i = blockIdx.x * 256 + threadIdx.x;
    if (i >= NTOT * KP) return;
    const int n = i / KP, k = i % KP;
    float v = 0.f;
    if (k < II) v = (n < G3) ? Wf[(size_t)n * II + k] : Wb[(size_t)(n - G3) * II + k];
    g_wt[i] = tf32r(v);
}

// ---------------------------------------------------------------------------
// Kernel 0b: x -> tf32-rounded fp32, K padded to 320. One thread = 8 cols.
// ---------------------------------------------------------------------------
__global__ void __launch_bounds__(256)
xprep_kernel(const float* __restrict__ x)
{
    const int task = blockIdx.x * 256 + threadIdx.x;   // MTOT*40 tasks
    if (task >= MTOT * 40) return;
    const int row = task / 40;
    const int c0  = (task % 40) * 8;

    const float* src = x + (size_t)row * II + c0;
    float4 v0 = make_float4(0.f, 0.f, 0.f, 0.f), v1 = v0;
    if (c0     <= 296) v0 = *(const float4*)src;
    if (c0 + 4 <= 296) v1 = *(const float4*)(src + 4);
    float4 o0, o1;
    o0.x = tf32r(v0.x); o0.y = tf32r(v0.y); o0.z = tf32r(v0.z); o0.w = tf32r(v0.w);
    o1.x = tf32r(v1.x); o1.y = tf32r(v1.y); o1.z = tf32r(v1.z); o1.w = tf32r(v1.w);
    const size_t di = (size_t)row * KP + c0;
    *(float4*)(g_xt + di)     = o0;
    *(float4*)(g_xt + di + 4) = o1;
}

// ---------------------------------------------------------------------------
// Kernel 1: proj GEMM via single-pass tf32 mma.sync (m16n8k8).
// CTA tile 128(M) x 128(N), 8 warps 2m x 4n (warp tile 64x32), K-chunk 64
// (8 k8 steps), 2-stage cp.async pipeline. Fragments via LDS.32 from rows
// padded to 68 floats (conflict-free). Grid (3 N fastest, 1024 M) -> L2 A reuse.
// ---------------------------------------------------------------------------
#define STG_FLOATS (256 * ROWF)            // A 128 rows + B 128 rows
#define STG_BYTES  (STG_FLOATS * 4)        // 69632
#define PROJ_SMEM  (2 * STG_BYTES)         // 139264

__global__ void __launch_bounds__(256, 1)
proj_kernel(const float* __restrict__ bf_, const float* __restrict__ bb_)
{
    extern __shared__ float dsm[];
    const u32 smem_base = smem_u32(dsm);

    const int tid    = threadIdx.x;
    const int lane   = tid & 31;
    const int wid    = tid >> 5;
    const int warp_m = wid & 1;          // 0..1
    const int warp_n = wid >> 1;         // 0..3
    const int r0     = blockIdx.y * 128; // M tile
    const int n0     = blockIdx.x * 128; // N tile (fastest -> L2 A reuse)

    float acc[4][4][4];
    #pragma unroll
    for (int i = 0; i < 4; i++)
        #pragma unroll
        for (int j = 0; j < 4; j++)
            #pragma unroll
            for (int q = 0; q < 4; q++) acc[i][j][q] = 0.f;

    // stage loader: 4096 cp16 (A 2048 | B 2048), 16 per thread
    auto load_stage = [&](int stg, int c) {
        const int k0 = c * 64;
        const u32 sb = smem_base + stg * STG_BYTES;
        #pragma unroll
        for (int it = 0; it < 16; it++) {
            const int t = tid + it * 256;
            const int side = t >> 11;            // 0 = A, 1 = B
            const int r = (t >> 4) & 127;
            const int q = t & 15;
            const u32 dst = sb + (u32)((side * 128 + r) * (ROWF * 4) + q * 16);
            const float* src = side
                ? g_wt + (size_t)(n0 + r) * KP + k0 + q * 4
                : g_xt + (size_t)(r0 + r) * KP + k0 + q * 4;
            cp16(dst, src);
        }
    };

    load_stage(0, 0);
    CP_COMMIT();

    const int rA = lane >> 2;   // 0..7
    const int cA = lane & 3;    // 0..3

    for (int c = 0; c < 5; c++) {
        if (c + 1 < 5) { load_stage((c + 1) & 1, c + 1); CP_COMMIT(); CP_WAIT(1); }
        else           { CP_WAIT(0); }
        __syncthreads();

        const float* As = dsm + (c & 1) * STG_FLOATS;
        const float* Bs = As + 128 * ROWF;

        #pragma unroll
        for (int g = 0; g < 8; g++) {
            u32 a[4][4], b[4][2];
            #pragma unroll
            for (int mi = 0; mi < 4; mi++) {
                const float* ap = As + (warp_m * 64 + mi * 16 + rA) * ROWF + g * 8 + cA;
                a[mi][0] = __float_as_uint(ap[0]);
                a[mi][1] = __float_as_uint(ap[8 * ROWF]);
                a[mi][2] = __float_as_uint(ap[4]);
                a[mi][3] = __float_as_uint(ap[8 * ROWF + 4]);
            }
            #pragma unroll
            for (int j = 0; j < 4; j++) {
                const float* bp = Bs + (warp_n * 32 + j * 8 + rA) * ROWF + g * 8 + cA;
                b[j][0] = __float_as_uint(bp[0]);
                b[j][1] = __float_as_uint(bp[4]);
            }
            #pragma unroll
            for (int mi = 0; mi < 4; mi++)
                #pragma unroll
                for (int j = 0; j < 4; j++)
                    mma_tf32(acc[mi][j], a[mi], b[j][0], b[j][1]);
        }
        __syncthreads();   // all warps done with this stage before it is refilled
    }

    // ---- epilogue: bias + scatter to g_xp in scan order ----
    #pragma unroll
    for (int j = 0; j < 4; j++) {
        const int col = n0 + warp_n * 32 + j * 8 + (lane & 3) * 2;
        const int dir = (col >= G3) ? 1 : 0;
        const int g   = col - dir * G3;
        const float2 bv = *(const float2*)((dir ? bb_ : bf_) + g);
        #pragma unroll
        for (int mi = 0; mi < 4; mi++) {
            #pragma unroll
            for (int h = 0; h < 2; h++) {
                const int r = r0 + warp_m * 64 + mi * 16 + (lane >> 2) + h * 8;
                const int b = r >> 9, t = r & 511;
                const int s = dir ? (TT - 1 - t) : t;
                float2 o;
                o.x = acc[mi][j][2*h]   + bv.x;
                o.y = acc[mi][j][2*h+1] + bv.y;
                *(float2*)&g_xp[(((size_t)dir * TT + s) * BB + b) * G3 + g] = o;
            }
        }
    }
}

// ---------------------------------------------------------------------------
// Kernel 2: GRU recurrence — R7 config (proven best). 1 chain per 128-thread
// block, 4 blocks/SM, pair-split weights, depth-8 cp.async xp ring.
// ---------------------------------------------------------------------------
__device__ __forceinline__ float sigmoid_fast(float a) {
    return 1.f / (1.f + __expf(-a));
}
__device__ __forceinline__ float tanh_fast(float a) {
    float c = fminf(fmaxf(a, -20.f), 20.f);
    float e = __expf(2.f * c);
    return (e - 1.f) / (e + 1.f);
}

__global__ void __launch_bounds__(128, 4)
gru_kernel(const float* __restrict__ Whh_f, const float* __restrict__ bhh_f,
           const float* __restrict__ Whh_b, const float* __restrict__ bhh_b)
{
    __shared__ __align__(16) float sh_h[2][64];
    __shared__ __align__(16) float ring[RING_D][192];

    const int tid  = threadIdx.x;
    const int j    = tid >> 1;
    const int half = tid & 1;
    const int dir  = blockIdx.x >> 8;
    const int b    = blockIdx.x & 255;

    const float* W  = dir ? Whh_b : Whh_f;
    const float* bh = dir ? bhh_b : bhh_f;

    ull wr[16], wz[16], wn[16];
    {
        const ulonglong2* Rr = (const ulonglong2*)(W + (size_t)j * 64         + half * 32);
        const ulonglong2* Rz = (const ulonglong2*)(W + (size_t)(j + 64) * 64  + half * 32);
        const ulonglong2* Rn = (const ulonglong2*)(W + (size_t)(j + 128) * 64 + half * 32);
        #pragma unroll
        for (int q = 0; q < 8; q++) {
            ((ulonglong2*)wr)[q] = Rr[q];
            ((ulonglong2*)wz)[q] = Rz[q];
            ((ulonglong2*)wn)[q] = Rn[q];
        }
    }
    const float br = bh[j], bz = bh[j + 64], bn = bh[j + 128];

    if (tid < 64) sh_h[0][tid] = 0.f;
    float h_old = 0.f;

    const float* xp_b = g_xp + ((size_t)dir * TT * BB + b) * G3;
    const size_t stride = (size_t)BB * G3;
    const u32 ring_base = smem_u32(ring);

    #pragma unroll
    for (int d = 0; d < RING_D; d++) {
        if (tid < 48)
            cp16(ring_base + (u32)(d * 768 + tid * 16),
                 xp_b + (size_t)d * stride + tid * 4);
        CP_COMMIT();
    }
    CP_WAIT(RING_D - 1);
    __syncthreads();

    #pragma unroll 1
    for (int s = 0; s < TT; s++) {
        const int slot = s & (RING_D - 1);
        const float* xp = ring[slot];
        const float xr = xp[j];
        const float xz = xp[j + 64];
        const float xn = xp[j + 128];

        const int pp = s & 1;
        const ulonglong2* hp = (const ulonglong2*)&sh_h[pp][half * 32];
        ull ar = 0ull, az = 0ull, an = 0ull;
        #pragma unroll
        for (int q = 0; q < 8; q++) {
            ulonglong2 h2 = hp[q];
            ar = ffma2(wr[2*q],   h2.x, ar);
            az = ffma2(wz[2*q],   h2.x, az);
            an = ffma2(wn[2*q],   h2.x, an);
            ar = ffma2(wr[2*q+1], h2.y, ar);
            az = ffma2(wz[2*q+1], h2.y, az);
            an = ffma2(wn[2*q+1], h2.y, an);
        }
        float gr = hsum2(ar), gz = hsum2(az), gn = hsum2(an);
        gr += __shfl_xor_sync(0xffffffffu, gr, 1);
        gz += __shfl_xor_sync(0xffffffffu, gz, 1);
        gn += __shfl_xor_sync(0xffffffffu, gn, 1);
        gr += br; gz += bz; gn += bn;

        const float r = sigmoid_fast(xr + gr);
        const float z = sigmoid_fast(xz + gz);
        const float n = tanh_fast(xn + r * gn);
        const float hnew = (1.f - z) * n + z * h_old;
        h_old = hnew;

        if (half == 0) {
            sh_h[1 - pp][j] = hnew;
            if (s == 0)
                g_feat[b * 256 + (dir ? 192 : 0) + j] = hnew;
        }

        CP_WAIT(RING_D - 2);
        __syncthreads();

        if (tid < 48)
            cp16(ring_base + (u32)(slot * 768 + tid * 16),
                 xp_b + (size_t)((s + RING_D) & (TT - 1)) * stride + tid * 4);
        CP_COMMIT();
    }

    if (half == 0)
        g_feat[b * 256 + (dir ? 64 : 128) + j] = h_old;
}

// ---------------------------------------------------------------------------
// Kernel 3: head. 8 warps per block, one warp per batch row; 32 blocks.
// ---------------------------------------------------------------------------
__global__ void __launch_bounds__(256)
head_kernel(const float* __restrict__ W1, const float* __restrict__ b1,
            const float* __restrict__ W2, const float* __restrict__ b2,
            float* __restrict__ out)
{
    const int wid = threadIdx.x >> 5;
    const int j   = threadIdx.x & 31;
    const int b   = blockIdx.x * 8 + wid;
    const float* f = g_feat + b * 256;
    const float* w = W1 + (size_t)j * 256;

    float acc = b1[j];
    #pragma unroll 8
    for (int k = 0; k < 256; k += 4) {
        float4 fv = *(const float4*)(f + k);
        float4 wv = *(const float4*)(w + k);
        acc += fv.x * wv.x + fv.y * wv.y + fv.z * wv.z + fv.w * wv.w;
    }
    acc = (acc >= 0.f) ? acc : 0.01f * acc;
    float v = acc * W2[j];
    #pragma unroll
    for (int off = 16; off; off >>= 1)
        v += __shfl_down_sync(0xffffffffu, v, off);
    if (j == 0) out[b] = v + b2[0];
}

// ---------------------------------------------------------------------------
extern "C" void kernel_launch(void* const* d_in, const int* in_sizes, int n_in,
                              void* d_out, int out_size)
{
    const float* x      = (const float*)d_in[0];
    const float* W_ih_f = (const float*)d_in[1];
    const float* W_hh_f = (const float*)d_in[2];
    const float* b_ih_f = (const float*)d_in[3];
    const float* b_hh_f = (const float*)d_in[4];
    const float* W_ih_b = (const float*)d_in[5];
    const float* W_hh_b = (const float*)d_in[6];
    const float* b_ih_b = (const float*)d_in[7];
    const float* b_hh_b = (const float*)d_in[8];
    const float* W1     = (const float*)d_in[9];
    const float* b1     = (const float*)d_in[10];
    const float* W2     = (const float*)d_in[11];
    const float* b2     = (const float*)d_in[12];
    float* out = (float*)d_out;

    cudaFuncSetAttribute(proj_kernel, cudaFuncAttributeMaxDynamicSharedMemorySize, PROJ_SMEM);

    wprep_kernel<<<(NTOT * KP + 255) / 256, 256>>>(W_ih_f, W_ih_b);
    xprep_kernel<<<(MTOT * 40 + 255) / 256, 256>>>(x);
    proj_kernel<<<dim3(3, 1024), 256, PROJ_SMEM>>>(b_ih_f, b_ih_b);
    gru_kernel<<<512, 128>>>(W_hh_f, b_hh_f, W_hh_b, b_hh_b);
    head_kernel<<<32, 256>>>(W1, b1, W2, b2, out);
}